// round 6
// baseline (speedup 1.0000x reference)
#include <cuda_runtime.h>

// RestrictedNN GB300. B=4096, NINP=4096, L0=512(G=8,H=16), L1=64, L2=8.
// k1: x -> (gene folded) -> h0 -> h1. 1 row per lane, warp = 32-row tile,
//     SIMD = h-pairs via fma.rn.f32x2, weights broadcast from smem, h0 in regs.
//     h1 stored TRANSPOSED: g_h1T[feature][row].
// k2: 512 thr: warp pairs (w, w+8) split module (w&7)'s 128 features;
//     root + final on warps 0-7. Explicit 16-wide LDG batches for MLP.
// Sigmoid inputs pre-scaled by -log2(e): sig(z) = rcp(1 + ex2(z)).

#define SCALE (-1.44269504f)

typedef unsigned long long u64;

__device__ float g_h1T[(size_t)1024 * 4096];   // [feature][row], 16 MB

__device__ __forceinline__ u64 pack2(float lo, float hi) {
    u64 r; asm("mov.b64 %0, {%1, %2};" : "=l"(r) : "f"(lo), "f"(hi)); return r;
}
__device__ __forceinline__ void unpack2(u64 v, float& lo, float& hi) {
    asm("mov.b64 {%0, %1}, %2;" : "=f"(lo), "=f"(hi) : "l"(v));
}
__device__ __forceinline__ u64 ffma2(u64 a, u64 b, u64 c) {
    u64 d; asm("fma.rn.f32x2 %0, %1, %2, %3;" : "=l"(d) : "l"(a), "l"(b), "l"(c));
    return d;
}
__device__ __forceinline__ u64 add2(u64 a, u64 b) {
    u64 d; asm("add.rn.f32x2 %0, %1, %2;" : "=l"(d) : "l"(a), "l"(b));
    return d;
}
__device__ __forceinline__ u64 sig2s(u64 z) {          // z pre-scaled
    float a, b; unpack2(z, a, b);
    float ea, eb, ra, rb;
    asm("ex2.approx.f32 %0, %1;" : "=f"(ea) : "f"(a));
    asm("ex2.approx.f32 %0, %1;" : "=f"(eb) : "f"(b));
    asm("rcp.approx.f32 %0, %1;" : "=f"(ra) : "f"(1.0f + ea));
    asm("rcp.approx.f32 %0, %1;" : "=f"(rb) : "f"(1.0f + eb));
    return pack2(ra, rb);
}

// ---------------------------------------------------------------------------
// K1: grid (16 tile-groups, 64 g), 256 threads = 8 warps; warp -> one 32-row
// tile, lane = row.
// ---------------------------------------------------------------------------
__global__ __launch_bounds__(256, 2) void k1(
    const float* __restrict__ x, const float* __restrict__ Wg,
    const float* __restrict__ bgp, const float* __restrict__ W0,
    const float* __restrict__ W1)
{
    __shared__ __align__(16) float w0ps[1024];    // [l][j][h] * Wg * SCALE
    __shared__ __align__(16) float bias0s[128];   // [l][h] * SCALE
    __shared__ __align__(16) float w1s[2048];     // [k][h] * SCALE

    const int g   = blockIdx.y;
    const int tid = threadIdx.x;

    {
        float4 v = ((const float4*)(W0 + (size_t)g * 1024))[tid];
        float wg = Wg[g * 64 + (tid >> 2)] * SCALE;
        float4 o; o.x = v.x * wg; o.y = v.y * wg; o.z = v.z * wg; o.w = v.w * wg;
        ((float4*)w0ps)[tid] = o;
    }
    #pragma unroll
    for (int it = 0; it < 2; ++it) {
        int i4 = tid + 256 * it;
        float4 v = ((const float4*)(W1 + (size_t)g * 2048))[i4];
        float4 o; o.x = v.x * SCALE; o.y = v.y * SCALE; o.z = v.z * SCALE; o.w = v.w * SCALE;
        ((float4*)w1s)[i4] = o;
    }
    if (tid < 128) {
        int l = tid >> 4, h = tid & 15;
        const float* bgl = bgp + g * 64 + l * 8;
        const float* w0l = W0 + (size_t)g * 1024 + l * 128 + h;
        float a = 0.f;
        #pragma unroll
        for (int j = 0; j < 8; ++j) a += bgl[j] * w0l[j * 16];
        bias0s[tid] = a * SCALE;
    }
    __syncthreads();

    const int warp = tid >> 5, lane = tid & 31;
    const int row  = (blockIdx.x * 8 + warp) * 32 + lane;
    const float* xr = x + (size_t)row * 4096 + g * 64;

    u64 acc1[8];
    #pragma unroll
    for (int hp = 0; hp < 8; ++hp) acc1[hp] = 0ull;

    float4 pa0 = __ldg((const float4*)xr), pa1 = __ldg((const float4*)xr + 1);

    #pragma unroll 1
    for (int l = 0; l < 8; ++l) {
        float xa[8];
        xa[0]=pa0.x; xa[1]=pa0.y; xa[2]=pa0.z; xa[3]=pa0.w;
        xa[4]=pa1.x; xa[5]=pa1.y; xa[6]=pa1.z; xa[7]=pa1.w;
        {
            int ln = (l + 1) & 7;
            pa0 = __ldg((const float4*)(xr + ln * 8));
            pa1 = __ldg((const float4*)(xr + ln * 8) + 1);
        }

        u64 acc0[8];
        #pragma unroll
        for (int hp = 0; hp < 8; ++hp)
            acc0[hp] = ((const u64*)bias0s)[l * 8 + hp];

        #pragma unroll
        for (int j = 0; j < 8; ++j) {
            u64 dA = pack2(xa[j], xa[j]);
            const ulonglong2* wrow = (const ulonglong2*)(w0ps + l * 128 + j * 16);
            #pragma unroll
            for (int hq = 0; hq < 4; ++hq) {
                ulonglong2 w = wrow[hq];                 // broadcast
                acc0[hq*2]   = ffma2(dA, w.x, acc0[hq*2]);
                acc0[hq*2+1] = ffma2(dA, w.y, acc0[hq*2+1]);
            }
        }

        // sigmoid(h0) -> accumulate into h1 (weights loaded 4 regs at a time)
        #pragma unroll
        for (int hp = 0; hp < 8; ++hp) {
            u64 s = sig2s(acc0[hp]);
            float s0, s1; unpack2(s, s0, s1);
            u64 d0 = pack2(s0, s0), d1 = pack2(s1, s1);
            const int k0 = l * 16 + hp * 2;
            {
                const ulonglong2* wr = (const ulonglong2*)(w1s + k0 * 16);
                ulonglong2 w0 = wr[0], w1 = wr[1], w2 = wr[2], w3 = wr[3];
                acc1[0] = ffma2(d0, w0.x, acc1[0]);
                acc1[1] = ffma2(d0, w0.y, acc1[1]);
                acc1[2] = ffma2(d0, w1.x, acc1[2]);
                acc1[3] = ffma2(d0, w1.y, acc1[3]);
                acc1[4] = ffma2(d0, w2.x, acc1[4]);
                acc1[5] = ffma2(d0, w2.y, acc1[5]);
                acc1[6] = ffma2(d0, w3.x, acc1[6]);
                acc1[7] = ffma2(d0, w3.y, acc1[7]);
            }
            {
                const ulonglong2* wr = (const ulonglong2*)(w1s + (k0 + 1) * 16);
                ulonglong2 w0 = wr[0], w1 = wr[1], w2 = wr[2], w3 = wr[3];
                acc1[0] = ffma2(d1, w0.x, acc1[0]);
                acc1[1] = ffma2(d1, w0.y, acc1[1]);
                acc1[2] = ffma2(d1, w1.x, acc1[2]);
                acc1[3] = ffma2(d1, w1.y, acc1[3]);
                acc1[4] = ffma2(d1, w2.x, acc1[4]);
                acc1[5] = ffma2(d1, w2.y, acc1[5]);
                acc1[6] = ffma2(d1, w3.x, acc1[6]);
                acc1[7] = ffma2(d1, w3.y, acc1[7]);
            }
        }
    }

    // finalize h1: sigmoid, store transposed (coalesced across lanes)
    #pragma unroll
    for (int hp = 0; hp < 8; ++hp) {
        u64 s = sig2s(acc1[hp]);
        float s0, s1; unpack2(s, s0, s1);
        g_h1T[(size_t)(g * 16 + hp * 2)     * 4096 + row] = s0;
        g_h1T[(size_t)(g * 16 + hp * 2 + 1) * 4096 + row] = s1;
    }
}

// ---------------------------------------------------------------------------
// K2: grid 128, 512 threads = 16 warps. lane = row (row0+lane).
// Warp w (0..15): module m=w&7, feature half (w>>3). Warps 8-15 dump partials
// to smem; warps 0-7 combine + sigmoid, then root + final.
// ---------------------------------------------------------------------------
#define H2S_FLOATS (32 * 129 + 4)   // +4 keeps the following u64 region 8B-aligned

__global__ __launch_bounds__(512) void k2(
    const float* __restrict__ W2, const float* __restrict__ W3,
    const float* __restrict__ Wf, float* __restrict__ out)
{
    extern __shared__ __align__(16) unsigned char smraw2[];
    float* w2s   = (float*)smraw2;             // [m][k][h] * SCALE, 16384 f
    float* w3s   = w2s + 16384;                // [k][h]  * SCALE, 2048 f
    float* h2s   = w3s + 2048;                 // [row_lane][129]
    u64*   part2 = (u64*)(h2s + H2S_FLOATS);   // h2 partials [hp][w][lane] 8x8x32
    u64*   part  = part2 + 2048;               // root partials [hp][w][lane]
    float* fpart = (float*)(part + 2048);      // [w][lane]

    const int tid  = threadIdx.x;
    const int warp = tid >> 5;
    const int lane = tid & 31;
    const int row0 = blockIdx.x * 32;
    const int m    = warp & 7;
    const int jb   = (warp >> 3) * 64;         // feature-half base

    // stage W2, W3 (pre-scaled), natural [k][h] layout
    #pragma unroll
    for (int it = 0; it < 8; ++it) {
        int i4 = tid + 512 * it;               // 4096 float4
        float4 v = ((const float4*)W2)[i4];
        float4 o; o.x = v.x * SCALE; o.y = v.y * SCALE; o.z = v.z * SCALE; o.w = v.w * SCALE;
        ((float4*)w2s)[i4] = o;
    }
    {
        int i4 = tid;                          // 512 float4
        float4 v = ((const float4*)W3)[i4];
        float4 o; o.x = v.x * SCALE; o.y = v.y * SCALE; o.z = v.z * SCALE; o.w = v.w * SCALE;
        ((float4*)w3s)[i4] = o;
    }
    __syncthreads();

    // ---- h2 partial: 64 features, explicit 16-wide load batches ----
    u64 acc[8];
    #pragma unroll
    for (int hp = 0; hp < 8; ++hp) acc[hp] = 0ull;
    {
        const float* actc = g_h1T + (size_t)(m * 128 + jb) * 4096 + row0 + lane;
        const float* wbase = w2s + (m * 128 + jb) * 16;

        float cur[16], nxt[16];
        #pragma unroll
        for (int t = 0; t < 16; ++t) cur[t] = __ldg(actc + (size_t)t * 4096);

        #pragma unroll
        for (int b = 0; b < 4; ++b) {
            if (b < 3) {
                #pragma unroll
                for (int t = 0; t < 16; ++t)
                    nxt[t] = __ldg(actc + (size_t)((b + 1) * 16 + t) * 4096);
            }
            #pragma unroll
            for (int t = 0; t < 16; ++t) {
                u64 d = pack2(cur[t], cur[t]);
                const ulonglong2* wr = (const ulonglong2*)(wbase + (b * 16 + t) * 16);
                ulonglong2 w0 = wr[0], w1 = wr[1], w2v = wr[2], w3v = wr[3];
                acc[0] = ffma2(d, w0.x,  acc[0]);
                acc[1] = ffma2(d, w0.y,  acc[1]);
                acc[2] = ffma2(d, w1.x,  acc[2]);
                acc[3] = ffma2(d, w1.y,  acc[3]);
                acc[4] = ffma2(d, w2v.x, acc[4]);
                acc[5] = ffma2(d, w2v.y, acc[5]);
                acc[6] = ffma2(d, w3v.x, acc[6]);
                acc[7] = ffma2(d, w3v.y, acc[7]);
            }
            #pragma unroll
            for (int t = 0; t < 16; ++t) cur[t] = nxt[t];
        }
    }
    if (warp >= 8) {
        #pragma unroll
        for (int hp = 0; hp < 8; ++hp)
            part2[hp * 256 + m * 32 + lane] = acc[hp];
    }
    __syncthreads();

    if (warp < 8) {
        #pragma unroll
        for (int hp = 0; hp < 8; ++hp) {
            u64 s = sig2s(add2(acc[hp], part2[hp * 256 + m * 32 + lane]));
            float s0, s1; unpack2(s, s0, s1);
            h2s[lane * 129 + m * 16 + hp * 2]     = s0;
            h2s[lane * 129 + m * 16 + hp * 2 + 1] = s1;
        }
    }
    __syncthreads();

    // ---- root partial: warp w (<8) covers k in [w*16, (w+1)*16) ----
    if (warp < 8) {
        u64 racc[8];
        #pragma unroll
        for (int hp = 0; hp < 8; ++hp) racc[hp] = 0ull;
        #pragma unroll
        for (int jj = 0; jj < 16; ++jj) {
            int jg = warp * 16 + jj;
            float a = h2s[lane * 129 + jg];
            u64 d = pack2(a, a);
            const ulonglong2* wr = (const ulonglong2*)(w3s + jg * 16);
            ulonglong2 w0 = wr[0], w1 = wr[1], w2v = wr[2], w3v = wr[3];
            racc[0] = ffma2(d, w0.x,  racc[0]);
            racc[1] = ffma2(d, w0.y,  racc[1]);
            racc[2] = ffma2(d, w1.x,  racc[2]);
            racc[3] = ffma2(d, w1.y,  racc[3]);
            racc[4] = ffma2(d, w2v.x, racc[4]);
            racc[5] = ffma2(d, w2v.y, racc[5]);
            racc[6] = ffma2(d, w3v.x, racc[6]);
            racc[7] = ffma2(d, w3v.y, racc[7]);
        }
        #pragma unroll
        for (int hp = 0; hp < 8; ++hp)
            part[hp * 256 + warp * 32 + lane] = racc[hp];
    }
    __syncthreads();

    // ---- reduce: warp w (<8) owns h-pair hp=w -> contrib = sig*Wf ----
    if (warp < 8) {
        u64 s = part[warp * 256 + lane];
        #pragma unroll
        for (int ww = 1; ww < 8; ++ww)
            s = add2(s, part[warp * 256 + ww * 32 + lane]);
        u64 sg = sig2s(s);
        float s0, s1; unpack2(sg, s0, s1);
        float c = s0 * __ldg(Wf + warp * 2) + s1 * __ldg(Wf + warp * 2 + 1);
        fpart[warp * 32 + lane] = c;
    }
    __syncthreads();

    if (warp == 0) {
        float a = fpart[lane];
        #pragma unroll
        for (int ww = 1; ww < 8; ++ww) a += fpart[ww * 32 + lane];
        out[row0 + lane] = a;
    }
}

static const int K2_SMEM = (16384 + 2048 + H2S_FLOATS) * 4 + 2048 * 8 + 2048 * 8 + 256 * 4;

extern "C" void kernel_launch(void* const* d_in, const int* in_sizes, int n_in,
                              void* d_out, int out_size)
{
    const float* x  = (const float*)d_in[0];
    const float* Wg = (const float*)d_in[1];
    const float* bg = (const float*)d_in[2];
    const float* W0 = (const float*)d_in[3];
    const float* W1 = (const float*)d_in[4];
    const float* W2 = (const float*)d_in[5];
    const float* W3 = (const float*)d_in[6];
    const float* Wf = (const float*)d_in[7];
    float* out = (float*)d_out;

    cudaFuncSetAttribute(k2, cudaFuncAttributeMaxDynamicSharedMemorySize, K2_SMEM);

    dim3 g1(16, 64);
    k1<<<g1, 256>>>(x, Wg, bg, W0, W1);
    k2<<<128, 512, K2_SMEM>>>(W2, W3, Wf, out);
}

// round 7
// speedup vs baseline: 1.1245x; 1.1245x over previous
#include <cuda_runtime.h>

// RestrictedNN GB300. B=4096, NINP=4096, L0=512(G=8,H=16), L1=64, L2=8.
// k1 (2 rows/lane, R5 structure): x -> gene-folded -> h0 -> h1.
//    h0 sigmoid via tanh.approx with affine fully folded into W1 staging:
//    sigmoid(z)=0.5 tanh(z/2)+0.5; w0/bias0 pre-scaled x0.5 (acc0=z/2);
//    w1s = 0.5*SCALE*W1, bias1 = 0.5*SCALE*sum_k W1 -> acc1 = SCALE*z1.
//    h1 output: exact ex2/rcp sigmoid, stored transposed g_h1T[feature][row].
// k2: grid 256 x 16-row blocks, 512 thr; warp=(module m, feature half),
//    lane=(row, feature parity); shfl_xor(16) combine; root+final on warps 0-7.

#define SCALE (-1.44269504f)

typedef unsigned long long u64;

__device__ float g_h1T[(size_t)1024 * 4096];   // [feature][row], 16 MB

__device__ __forceinline__ u64 pack2(float lo, float hi) {
    u64 r; asm("mov.b64 %0, {%1, %2};" : "=l"(r) : "f"(lo), "f"(hi)); return r;
}
__device__ __forceinline__ void unpack2(u64 v, float& lo, float& hi) {
    asm("mov.b64 {%0, %1}, %2;" : "=f"(lo), "=f"(hi) : "l"(v));
}
__device__ __forceinline__ u64 ffma2(u64 a, u64 b, u64 c) {
    u64 d; asm("fma.rn.f32x2 %0, %1, %2, %3;" : "=l"(d) : "l"(a), "l"(b), "l"(c));
    return d;
}
__device__ __forceinline__ u64 add2(u64 a, u64 b) {
    u64 d; asm("add.rn.f32x2 %0, %1, %2;" : "=l"(d) : "l"(a), "l"(b));
    return d;
}
__device__ __forceinline__ float tanhap(float z) {
    float t; asm("tanh.approx.f32 %0, %1;" : "=f"(t) : "f"(z)); return t;
}
__device__ __forceinline__ u64 sig2s(u64 z) {          // z pre-scaled by -log2e
    float a, b; unpack2(z, a, b);
    float ea, eb, ra, rb;
    asm("ex2.approx.f32 %0, %1;" : "=f"(ea) : "f"(a));
    asm("ex2.approx.f32 %0, %1;" : "=f"(eb) : "f"(b));
    asm("rcp.approx.f32 %0, %1;" : "=f"(ra) : "f"(1.0f + ea));
    asm("rcp.approx.f32 %0, %1;" : "=f"(rb) : "f"(1.0f + eb));
    return pack2(ra, rb);
}

// ---------------------------------------------------------------------------
// K1: grid (8 tile-groups, 64 g), 256 threads = 8 warps; warp -> one 64-row
// tile. Lane p handles rows (tile*64+p, tile*64+p+32).
// ---------------------------------------------------------------------------
__global__ __launch_bounds__(256) void k1(
    const float* __restrict__ x, const float* __restrict__ Wg,
    const float* __restrict__ bgp, const float* __restrict__ W0,
    const float* __restrict__ W1)
{
    __shared__ __align__(16) float w0ps[1024];    // [l][j][h] * Wg * 0.5
    __shared__ __align__(16) float bias0s[128];   // [l][h] * 0.5
    __shared__ __align__(16) float w1s[2048];     // [k][h] * 0.5 * SCALE
    __shared__ __align__(16) float bias1s[16];    // 0.5*SCALE*sum_k W1[k][h]

    const int g   = blockIdx.y;
    const int tid = threadIdx.x;

    {
        float4 v = ((const float4*)(W0 + (size_t)g * 1024))[tid];
        float wg = Wg[g * 64 + (tid >> 2)] * 0.5f;
        float4 o; o.x = v.x * wg; o.y = v.y * wg; o.z = v.z * wg; o.w = v.w * wg;
        ((float4*)w0ps)[tid] = o;
    }
    #pragma unroll
    for (int it = 0; it < 2; ++it) {
        int i4 = tid + 256 * it;
        float4 v = ((const float4*)(W1 + (size_t)g * 2048))[i4];
        const float s = 0.5f * SCALE;
        float4 o; o.x = v.x * s; o.y = v.y * s; o.z = v.z * s; o.w = v.w * s;
        ((float4*)w1s)[i4] = o;
    }
    if (tid < 128) {
        int l = tid >> 4, h = tid & 15;
        const float* bgl = bgp + g * 64 + l * 8;
        const float* w0l = W0 + (size_t)g * 1024 + l * 128 + h;
        float a = 0.f;
        #pragma unroll
        for (int j = 0; j < 8; ++j) a += bgl[j] * w0l[j * 16];
        bias0s[tid] = a * 0.5f;
    }
    __syncthreads();
    if (tid < 16) {
        float a = 0.f;
        for (int k = 0; k < 128; ++k) a += w1s[k * 16 + tid];  // already scaled
        bias1s[tid] = a;
    }
    __syncthreads();

    const int warp = tid >> 5, lane = tid & 31;
    const int tile = blockIdx.x * 8 + warp;
    const int rA = tile * 64 + lane;
    const int rB = rA + 32;
    const float* xA = x + (size_t)rA * 4096 + g * 64;
    const float* xB = x + (size_t)rB * 4096 + g * 64;

    u64 acc1[2][8];
    #pragma unroll
    for (int hp = 0; hp < 8; ++hp) {
        u64 b = ((const u64*)bias1s)[hp];
        acc1[0][hp] = b; acc1[1][hp] = b;
    }

    float4 pa0 = __ldg((const float4*)xA), pa1 = __ldg((const float4*)xA + 1);
    float4 pb0 = __ldg((const float4*)xB), pb1 = __ldg((const float4*)xB + 1);

    #pragma unroll 1
    for (int l = 0; l < 8; ++l) {
        float xa[8], xb[8];
        xa[0]=pa0.x; xa[1]=pa0.y; xa[2]=pa0.z; xa[3]=pa0.w;
        xa[4]=pa1.x; xa[5]=pa1.y; xa[6]=pa1.z; xa[7]=pa1.w;
        xb[0]=pb0.x; xb[1]=pb0.y; xb[2]=pb0.z; xb[3]=pb0.w;
        xb[4]=pb1.x; xb[5]=pb1.y; xb[6]=pb1.z; xb[7]=pb1.w;
        {
            int ln = (l + 1) & 7;
            pa0 = __ldg((const float4*)(xA + ln * 8));
            pa1 = __ldg((const float4*)(xA + ln * 8) + 1);
            pb0 = __ldg((const float4*)(xB + ln * 8));
            pb1 = __ldg((const float4*)(xB + ln * 8) + 1);
        }

        u64 acc0[2][8];
        #pragma unroll
        for (int hp = 0; hp < 8; ++hp) {
            u64 b = ((const u64*)bias0s)[l * 8 + hp];
            acc0[0][hp] = b; acc0[1][hp] = b;
        }
        #pragma unroll
        for (int j = 0; j < 8; ++j) {
            u64 dA = pack2(xa[j], xa[j]);
            u64 dB = pack2(xb[j], xb[j]);
            const ulonglong2* wrow = (const ulonglong2*)(w0ps + l * 128 + j * 16);
            #pragma unroll
            for (int hq = 0; hq < 4; ++hq) {
                ulonglong2 w = wrow[hq];                 // broadcast
                acc0[0][hq*2]   = ffma2(dA, w.x, acc0[0][hq*2]);
                acc0[0][hq*2+1] = ffma2(dA, w.y, acc0[0][hq*2+1]);
                acc0[1][hq*2]   = ffma2(dB, w.x, acc0[1][hq*2]);
                acc0[1][hq*2+1] = ffma2(dB, w.y, acc0[1][hq*2+1]);
            }
        }

        // tanh(h0/2) -> accumulate straight into h1 (affine folded into w1s)
        #pragma unroll
        for (int hp = 0; hp < 8; ++hp) {
            const int k0 = l * 16 + hp * 2;
            const ulonglong2* wr0 = (const ulonglong2*)(w1s + k0 * 16);
            const ulonglong2* wr1 = (const ulonglong2*)(w1s + (k0 + 1) * 16);
            ulonglong2 wa0 = wr0[0], wa1 = wr0[1], wa2 = wr0[2], wa3 = wr0[3];
            ulonglong2 wb0 = wr1[0], wb1 = wr1[1], wb2 = wr1[2], wb3 = wr1[3];
            #pragma unroll
            for (int r = 0; r < 2; ++r) {
                float a0, a1; unpack2(acc0[r][hp], a0, a1);
                float t0 = tanhap(a0), t1 = tanhap(a1);
                u64 d0 = pack2(t0, t0), d1 = pack2(t1, t1);
                acc1[r][0] = ffma2(d0, wa0.x, acc1[r][0]);
                acc1[r][1] = ffma2(d0, wa0.y, acc1[r][1]);
                acc1[r][2] = ffma2(d0, wa1.x, acc1[r][2]);
                acc1[r][3] = ffma2(d0, wa1.y, acc1[r][3]);
                acc1[r][4] = ffma2(d0, wa2.x, acc1[r][4]);
                acc1[r][5] = ffma2(d0, wa2.y, acc1[r][5]);
                acc1[r][6] = ffma2(d0, wa3.x, acc1[r][6]);
                acc1[r][7] = ffma2(d0, wa3.y, acc1[r][7]);
                acc1[r][0] = ffma2(d1, wb0.x, acc1[r][0]);
                acc1[r][1] = ffma2(d1, wb0.y, acc1[r][1]);
                acc1[r][2] = ffma2(d1, wb1.x, acc1[r][2]);
                acc1[r][3] = ffma2(d1, wb1.y, acc1[r][3]);
                acc1[r][4] = ffma2(d1, wb2.x, acc1[r][4]);
                acc1[r][5] = ffma2(d1, wb2.y, acc1[r][5]);
                acc1[r][6] = ffma2(d1, wb3.x, acc1[r][6]);
                acc1[r][7] = ffma2(d1, wb3.y, acc1[r][7]);
            }
        }
    }

    // finalize h1: exact sigmoid (acc1 = SCALE*z1), store transposed
    #pragma unroll
    for (int r = 0; r < 2; ++r) {
        const int row = r ? rB : rA;
        #pragma unroll
        for (int hp = 0; hp < 8; ++hp) {
            u64 s = sig2s(acc1[r][hp]);
            float s0, s1; unpack2(s, s0, s1);
            g_h1T[(size_t)(g * 16 + hp * 2)     * 4096 + row] = s0;
            g_h1T[(size_t)(g * 16 + hp * 2 + 1) * 4096 + row] = s1;
        }
    }
}

// ---------------------------------------------------------------------------
// K2: grid 256 x 16 rows, 512 threads = 16 warps.
// warp w: module m=w&7, feature half (w>>3)*64. lane: row=lane&15,
// feature parity p=lane>>4 (32 features each, stride 2). shfl_xor(16) combine.
// ---------------------------------------------------------------------------
#define H2S_FLOATS (16 * 129 + 4)

__global__ __launch_bounds__(512, 2) void k2(
    const float* __restrict__ W2, const float* __restrict__ W3,
    const float* __restrict__ Wf, float* __restrict__ out)
{
    extern __shared__ __align__(16) unsigned char smraw2[];
    float* w2s   = (float*)smraw2;             // [m][k][h] * SCALE, 16384 f
    float* w3s   = w2s + 16384;                // [k][h]  * SCALE, 2048 f
    float* h2s   = w3s + 2048;                 // [row][129]
    u64*   part2 = (u64*)(h2s + H2S_FLOATS);   // [hp][m][row] = 8*8*16
    u64*   part  = part2 + 1024;               // [hp][w][row] = 8*8*16
    float* fpart = (float*)(part + 1024);      // [w][row] = 8*16

    const int tid  = threadIdx.x;
    const int warp = tid >> 5;
    const int lane = tid & 31;
    const int row  = lane & 15;
    const int par  = lane >> 4;
    const int row0 = blockIdx.x * 16;
    const int m    = warp & 7;
    const int fb   = m * 128 + (warp >> 3) * 64 + par;   // feature base, stride 2

    // stage W2, W3 (pre-scaled), natural [k][h] layout
    #pragma unroll
    for (int it = 0; it < 8; ++it) {
        int i4 = tid + 512 * it;               // 4096 float4
        float4 v = ((const float4*)W2)[i4];
        float4 o; o.x = v.x * SCALE; o.y = v.y * SCALE; o.z = v.z * SCALE; o.w = v.w * SCALE;
        ((float4*)w2s)[i4] = o;
    }
    {
        float4 v = ((const float4*)W3)[tid];   // 512 float4
        float4 o; o.x = v.x * SCALE; o.y = v.y * SCALE; o.z = v.z * SCALE; o.w = v.w * SCALE;
        ((float4*)w3s)[tid] = o;
    }
    __syncthreads();

    // ---- h2 partial: 32 features (stride 2), 8-wide load batches ----
    u64 acc[8];
    #pragma unroll
    for (int hp = 0; hp < 8; ++hp) acc[hp] = 0ull;
    {
        const float* actc = g_h1T + (size_t)fb * 4096 + row0 + row;
        const float* wbase = w2s + fb * 16;

        float cur[8], nxt[8];
        #pragma unroll
        for (int t = 0; t < 8; ++t) cur[t] = __ldg(actc + (size_t)(2 * t) * 4096);

        #pragma unroll
        for (int b = 0; b < 4; ++b) {
            if (b < 3) {
                #pragma unroll
                for (int t = 0; t < 8; ++t)
                    nxt[t] = __ldg(actc + (size_t)(2 * ((b + 1) * 8 + t)) * 4096);
            }
            #pragma unroll
            for (int t = 0; t < 8; ++t) {
                u64 d = pack2(cur[t], cur[t]);
                const ulonglong2* wr =
                    (const ulonglong2*)(wbase + 2 * (b * 8 + t) * 16);
                ulonglong2 w0 = wr[0], w1 = wr[1], w2v = wr[2], w3v = wr[3];
                acc[0] = ffma2(d, w0.x,  acc[0]);
                acc[1] = ffma2(d, w0.y,  acc[1]);
                acc[2] = ffma2(d, w1.x,  acc[2]);
                acc[3] = ffma2(d, w1.y,  acc[3]);
                acc[4] = ffma2(d, w2v.x, acc[4]);
                acc[5] = ffma2(d, w2v.y, acc[5]);
                acc[6] = ffma2(d, w3v.x, acc[6]);
                acc[7] = ffma2(d, w3v.y, acc[7]);
            }
            #pragma unroll
            for (int t = 0; t < 8; ++t) cur[t] = nxt[t];
        }
    }
    // combine feature parities within warp
    #pragma unroll
    for (int hp = 0; hp < 8; ++hp)
        acc[hp] = add2(acc[hp], __shfl_xor_sync(0xffffffffu, acc[hp], 16));

    if (warp >= 8 && par == 0) {
        #pragma unroll
        for (int hp = 0; hp < 8; ++hp)
            part2[hp * 128 + m * 16 + row] = acc[hp];
    }
    __syncthreads();

    if (warp < 8 && par == 0) {
        #pragma unroll
        for (int hp = 0; hp < 8; ++hp) {
            u64 s = sig2s(add2(acc[hp], part2[hp * 128 + m * 16 + row]));
            float s0, s1; unpack2(s, s0, s1);
            h2s[row * 129 + m * 16 + hp * 2]     = s0;
            h2s[row * 129 + m * 16 + hp * 2 + 1] = s1;
        }
    }
    __syncthreads();

    // ---- root partial: warp w (<8) covers k in [w*16, (w+1)*16) ----
    if (warp < 8) {
        u64 racc[8];
        #pragma unroll
        for (int hp = 0; hp < 8; ++hp) racc[hp] = 0ull;
        #pragma unroll
        for (int jj = 0; jj < 16; ++jj) {
            int jg = warp * 16 + jj;
            float a = h2s[row * 129 + jg];
            u64 d = pack2(a, a);
            const ulonglong2* wr = (const ulonglong2*)(w3s + jg * 16);
            ulonglong2 w0 = wr[0], w1 = wr[1], w2v = wr[2], w3v = wr[3];
            racc[0] = ffma2(d, w0.x,  racc[0]);
            racc[1] = ffma2(d, w0.y,  racc[1]);
            racc[2] = ffma2(d, w1.x,  racc[2]);
            racc[3] = ffma2(d, w1.y,  racc[3]);
            racc[4] = ffma2(d, w2v.x, racc[4]);
            racc[5] = ffma2(d, w2v.y, racc[5]);
            racc[6] = ffma2(d, w3v.x, racc[6]);
            racc[7] = ffma2(d, w3v.y, racc[7]);
        }
        if (par == 0) {
            #pragma unroll
            for (int hp = 0; hp < 8; ++hp)
                part[hp * 128 + warp * 16 + row] = racc[hp];
        }
    }
    __syncthreads();

    // ---- reduce: warp w (<8) owns h-pair hp=w ----
    if (warp < 8 && par == 0) {
        u64 s = part[warp * 128 + row];
        #pragma unroll
        for (int ww = 1; ww < 8; ++ww)
            s = add2(s, part[warp * 128 + ww * 16 + row]);
        u64 sg = sig2s(s);
        float s0, s1; unpack2(sg, s0, s1);
        float c = s0 * __ldg(Wf + warp * 2) + s1 * __ldg(Wf + warp * 2 + 1);
        fpart[warp * 16 + row] = c;
    }
    __syncthreads();

    if (warp == 0 && par == 0) {
        float a = fpart[row];
        #pragma unroll
        for (int ww = 1; ww < 8; ++ww) a += fpart[ww * 16 + row];
        out[row0 + row] = a;
    }
}

static const int K2_SMEM = (16384 + 2048 + H2S_FLOATS) * 4 + 1024 * 8 + 1024 * 8 + 128 * 4;

extern "C" void kernel_launch(void* const* d_in, const int* in_sizes, int n_in,
                              void* d_out, int out_size)
{
    const float* x  = (const float*)d_in[0];
    const float* Wg = (const float*)d_in[1];
    const float* bg = (const float*)d_in[2];
    const float* W0 = (const float*)d_in[3];
    const float* W1 = (const float*)d_in[4];
    const float* W2 = (const float*)d_in[5];
    const float* W3 = (const float*)d_in[6];
    const float* Wf = (const float*)d_in[7];
    float* out = (float*)d_out;

    cudaFuncSetAttribute(k2, cudaFuncAttributeMaxDynamicSharedMemorySize, K2_SMEM);

    dim3 g1(8, 64);
    k1<<<g1, 256>>>(x, Wg, bg, W0, W1);
    k2<<<256, 512, K2_SMEM>>>(W2, W3, Wf, out);
}

// round 11
// speedup vs baseline: 1.1997x; 1.0669x over previous
#include <cuda_runtime.h>
#include <cuda_fp16.h>

// RestrictedNN GB300. B=4096, NINP=4096, L0=512(G=8,H=16), L1=64, L2=8.
// k1 (2 rows/lane): x -> gene-folded -> h0 -> h1.
//    h0 sigmoid via tanh.approx, affine folded into w1s/bias1 staging.
//    h1: exact ex2/rcp sigmoid, stored transposed fp16: g_h1h[feature][row].
//    Low-reg h1 inner (tanh first, weights streamed 2xulonglong2) + 2 blocks/SM.
// k2: grid 256 x 16-row blocks, 512 thr; warp=(module, feature half),
//    lane=(row, feature parity); shfl_xor(16) combine; root+final on warps 0-7.

#define SCALE (-1.44269504f)

typedef unsigned long long u64;

__device__ __half g_h1h[(size_t)1024 * 4096];   // [feature][row], 8 MB

__device__ __forceinline__ u64 pack2(float lo, float hi) {
    u64 r; asm("mov.b64 %0, {%1, %2};" : "=l"(r) : "f"(lo), "f"(hi)); return r;
}
__device__ __forceinline__ void unpack2(u64 v, float& lo, float& hi) {
    asm("mov.b64 {%0, %1}, %2;" : "=f"(lo), "=f"(hi) : "l"(v));
}
__device__ __forceinline__ u64 ffma2(u64 a, u64 b, u64 c) {
    u64 d; asm("fma.rn.f32x2 %0, %1, %2, %3;" : "=l"(d) : "l"(a), "l"(b), "l"(c));
    return d;
}
__device__ __forceinline__ u64 add2(u64 a, u64 b) {
    u64 d; asm("add.rn.f32x2 %0, %1, %2;" : "=l"(d) : "l"(a), "l"(b));
    return d;
}
__device__ __forceinline__ float tanhap(float z) {
    float t; asm("tanh.approx.f32 %0, %1;" : "=f"(t) : "f"(z)); return t;
}
__device__ __forceinline__ u64 sig2s(u64 z) {          // z pre-scaled by -log2e
    float a, b; unpack2(z, a, b);
    float ea, eb, ra, rb;
    asm("ex2.approx.f32 %0, %1;" : "=f"(ea) : "f"(a));
    asm("ex2.approx.f32 %0, %1;" : "=f"(eb) : "f"(b));
    asm("rcp.approx.f32 %0, %1;" : "=f"(ra) : "f"(1.0f + ea));
    asm("rcp.approx.f32 %0, %1;" : "=f"(rb) : "f"(1.0f + eb));
    return pack2(ra, rb);
}

// ---------------------------------------------------------------------------
// K1: grid (8 tile-groups, 64 g), 256 threads = 8 warps; warp -> one 64-row
// tile. Lane p handles rows (tile*64+p, tile*64+p+32).
// ---------------------------------------------------------------------------
__global__ __launch_bounds__(256, 2) void k1(
    const float* __restrict__ x, const float* __restrict__ Wg,
    const float* __restrict__ bgp, const float* __restrict__ W0,
    const float* __restrict__ W1)
{
    __shared__ __align__(16) float w0ps[1024];    // [l][j][h] * Wg * 0.5
    __shared__ __align__(16) float bias0s[128];   // [l][h] * 0.5
    __shared__ __align__(16) float w1s[2048];     // [k][h] * 0.5 * SCALE
    __shared__ __align__(16) float bias1s[16];    // 0.5*SCALE*sum_k W1[k][h]

    const int g   = blockIdx.y;
    const int tid = threadIdx.x;

    {
        float4 v = ((const float4*)(W0 + (size_t)g * 1024))[tid];
        float wg = Wg[g * 64 + (tid >> 2)] * 0.5f;
        float4 o; o.x = v.x * wg; o.y = v.y * wg; o.z = v.z * wg; o.w = v.w * wg;
        ((float4*)w0ps)[tid] = o;
    }
    #pragma unroll
    for (int it = 0; it < 2; ++it) {
        int i4 = tid + 256 * it;
        float4 v = ((const float4*)(W1 + (size_t)g * 2048))[i4];
        const float s = 0.5f * SCALE;
        float4 o; o.x = v.x * s; o.y = v.y * s; o.z = v.z * s; o.w = v.w * s;
        ((float4*)w1s)[i4] = o;
    }
    if (tid < 128) {
        int l = tid >> 4, h = tid & 15;
        const float* bgl = bgp + g * 64 + l * 8;
        const float* w0l = W0 + (size_t)g * 1024 + l * 128 + h;
        float a = 0.f;
        #pragma unroll
        for (int j = 0; j < 8; ++j) a += bgl[j] * w0l[j * 16];
        bias0s[tid] = a * 0.5f;
    }
    __syncthreads();
    if (tid < 16) {
        float a = 0.f;
        for (int k = 0; k < 128; ++k) a += w1s[k * 16 + tid];  // already scaled
        bias1s[tid] = a;
    }
    __syncthreads();

    const int warp = tid >> 5, lane = tid & 31;
    const int tile = blockIdx.x * 8 + warp;
    const int rA = tile * 64 + lane;
    const int rB = rA + 32;
    const float* xA = x + (size_t)rA * 4096 + g * 64;
    const float* xB = x + (size_t)rB * 4096 + g * 64;

    u64 acc1[2][8];
    #pragma unroll
    for (int hp = 0; hp < 8; ++hp) {
        u64 b = ((const u64*)bias1s)[hp];
        acc1[0][hp] = b; acc1[1][hp] = b;
    }

    float4 pa0 = __ldg((const float4*)xA), pa1 = __ldg((const float4*)xA + 1);
    float4 pb0 = __ldg((const float4*)xB), pb1 = __ldg((const float4*)xB + 1);

    #pragma unroll 1
    for (int l = 0; l < 8; ++l) {
        float xa[8], xb[8];
        xa[0]=pa0.x; xa[1]=pa0.y; xa[2]=pa0.z; xa[3]=pa0.w;
        xa[4]=pa1.x; xa[5]=pa1.y; xa[6]=pa1.z; xa[7]=pa1.w;
        xb[0]=pb0.x; xb[1]=pb0.y; xb[2]=pb0.z; xb[3]=pb0.w;
        xb[4]=pb1.x; xb[5]=pb1.y; xb[6]=pb1.z; xb[7]=pb1.w;
        {
            int ln = (l + 1) & 7;
            pa0 = __ldg((const float4*)(xA + ln * 8));
            pa1 = __ldg((const float4*)(xA + ln * 8) + 1);
            pb0 = __ldg((const float4*)(xB + ln * 8));
            pb1 = __ldg((const float4*)(xB + ln * 8) + 1);
        }

        u64 acc0[2][8];
        #pragma unroll
        for (int hp = 0; hp < 8; ++hp) {
            u64 b = ((const u64*)bias0s)[l * 8 + hp];
            acc0[0][hp] = b; acc0[1][hp] = b;
        }
        #pragma unroll
        for (int j = 0; j < 8; ++j) {
            u64 dA = pack2(xa[j], xa[j]);
            u64 dB = pack2(xb[j], xb[j]);
            const ulonglong2* wrow = (const ulonglong2*)(w0ps + l * 128 + j * 16);
            #pragma unroll
            for (int hq = 0; hq < 4; ++hq) {
                ulonglong2 w = wrow[hq];                 // broadcast
                acc0[0][hq*2]   = ffma2(dA, w.x, acc0[0][hq*2]);
                acc0[0][hq*2+1] = ffma2(dA, w.y, acc0[0][hq*2+1]);
                acc0[1][hq*2]   = ffma2(dB, w.x, acc0[1][hq*2]);
                acc0[1][hq*2+1] = ffma2(dB, w.y, acc0[1][hq*2+1]);
            }
        }

        // tanh(h0/2) -> accumulate into h1; low-reg: tanh first, weights
        // streamed 2 x ulonglong2 per chunk (affine folded into w1s/bias1s)
        #pragma unroll
        for (int hp = 0; hp < 8; ++hp) {
            u64 dk0[2], dk1[2];
            #pragma unroll
            for (int r = 0; r < 2; ++r) {
                float a0, a1; unpack2(acc0[r][hp], a0, a1);
                float t0 = tanhap(a0), t1 = tanhap(a1);
                dk0[r] = pack2(t0, t0); dk1[r] = pack2(t1, t1);
            }
            const int k0 = l * 16 + hp * 2;
            const ulonglong2* wr0 = (const ulonglong2*)(w1s + k0 * 16);
            const ulonglong2* wr1 = (const ulonglong2*)(w1s + (k0 + 1) * 16);
            #pragma unroll
            for (int c = 0; c < 4; ++c) {
                ulonglong2 A = wr0[c];
                ulonglong2 B = wr1[c];
                #pragma unroll
                for (int r = 0; r < 2; ++r) {
                    acc1[r][c*2]   = ffma2(dk0[r], A.x, acc1[r][c*2]);
                    acc1[r][c*2+1] = ffma2(dk0[r], A.y, acc1[r][c*2+1]);
                    acc1[r][c*2]   = ffma2(dk1[r], B.x, acc1[r][c*2]);
                    acc1[r][c*2+1] = ffma2(dk1[r], B.y, acc1[r][c*2+1]);
                }
            }
        }
    }

    // finalize h1: exact sigmoid (acc1 = SCALE*z1), store transposed fp16
    #pragma unroll
    for (int r = 0; r < 2; ++r) {
        const int row = r ? rB : rA;
        #pragma unroll
        for (int hp = 0; hp < 8; ++hp) {
            u64 s = sig2s(acc1[r][hp]);
            float s0, s1; unpack2(s, s0, s1);
            g_h1h[(size_t)(g * 16 + hp * 2)     * 4096 + row] = __float2half(s0);
            g_h1h[(size_t)(g * 16 + hp * 2 + 1) * 4096 + row] = __float2half(s1);
        }
    }
}

// ---------------------------------------------------------------------------
// K2: grid 256 x 16 rows, 512 threads = 16 warps.
// warp w: module m=w&7, feature half (w>>3)*64. lane: row=lane&15,
// feature parity p=lane>>4 (32 features each, stride 2). shfl_xor(16) combine.
// ---------------------------------------------------------------------------
#define H2S_FLOATS (16 * 129 + 4)

__global__ __launch_bounds__(512, 2) void k2(
    const float* __restrict__ W2, const float* __restrict__ W3,
    const float* __restrict__ Wf, float* __restrict__ out)
{
    extern __shared__ __align__(16) unsigned char smraw2[];
    float* w2s   = (float*)smraw2;             // [m][k][h] * SCALE, 16384 f
    float* w3s   = w2s + 16384;                // [k][h]  * SCALE, 2048 f
    float* h2s   = w3s + 2048;                 // [row][129]
    u64*   part2 = (u64*)(h2s + H2S_FLOATS);   // [hp][m][row] = 8*8*16
    u64*   part  = part2 + 1024;               // [hp][w][row] = 8*8*16
    float* fpart = (float*)(part + 1024);      // [w][row] = 8*16

    const int tid  = threadIdx.x;
    const int warp = tid >> 5;
    const int lane = tid & 31;
    const int row  = lane & 15;
    const int par  = lane >> 4;
    const int row0 = blockIdx.x * 16;
    const int m    = warp & 7;
    const int fb   = m * 128 + (warp >> 3) * 64 + par;   // feature base, stride 2

    // stage W2, W3 (pre-scaled), natural [k][h] layout
    #pragma unroll
    for (int it = 0; it < 8; ++it) {
        int i4 = tid + 512 * it;               // 4096 float4
        float4 v = ((const float4*)W2)[i4];
        float4 o; o.x = v.x * SCALE; o.y = v.y * SCALE; o.z = v.z * SCALE; o.w = v.w * SCALE;
        ((float4*)w2s)[i4] = o;
    }
    {
        float4 v = ((const float4*)W3)[tid];   // 512 float4
        float4 o; o.x = v.x * SCALE; o.y = v.y * SCALE; o.z = v.z * SCALE; o.w = v.w * SCALE;
        ((float4*)w3s)[tid] = o;
    }
    __syncthreads();

    // ---- h2 partial: 32 features (stride 2), 8-wide load batches ----
    u64 acc[8];
    #pragma unroll
    for (int hp = 0; hp < 8; ++hp) acc[hp] = 0ull;
    {
        const __half* actc = g_h1h + (size_t)fb * 4096 + row0 + row;
        const float* wbase = w2s + fb * 16;

        float cur[8], nxt[8];
        #pragma unroll
        for (int t = 0; t < 8; ++t)
            cur[t] = __half2float(__ldg(actc + (size_t)(2 * t) * 4096));

        #pragma unroll
        for (int b = 0; b < 4; ++b) {
            if (b < 3) {
                #pragma unroll
                for (int t = 0; t < 8; ++t)
                    nxt[t] = __half2float(
                        __ldg(actc + (size_t)(2 * ((b + 1) * 8 + t)) * 4096));
            }
            #pragma unroll
            for (int t = 0; t < 8; ++t) {
                u64 d = pack2(cur[t], cur[t]);
                const ulonglong2* wr =
                    (const ulonglong2*)(wbase + 2 * (b * 8 + t) * 16);
                ulonglong2 w0 = wr[0], w1 = wr[1], w2v = wr[2], w3v = wr[3];
                acc[0] = ffma2(d, w0.x,  acc[0]);
                acc[1] = ffma2(d, w0.y,  acc[1]);
                acc[2] = ffma2(d, w1.x,  acc[2]);
                acc[3] = ffma2(d, w1.y,  acc[3]);
                acc[4] = ffma2(d, w2v.x, acc[4]);
                acc[5] = ffma2(d, w2v.y, acc[5]);
                acc[6] = ffma2(d, w3v.x, acc[6]);
                acc[7] = ffma2(d, w3v.y, acc[7]);
            }
            #pragma unroll
            for (int t = 0; t < 8; ++t) cur[t] = nxt[t];
        }
    }
    // combine feature parities within warp
    #pragma unroll
    for (int hp = 0; hp < 8; ++hp)
        acc[hp] = add2(acc[hp], __shfl_xor_sync(0xffffffffu, acc[hp], 16));

    if (warp >= 8 && par == 0) {
        #pragma unroll
        for (int hp = 0; hp < 8; ++hp)
            part2[hp * 128 + m * 16 + row] = acc[hp];
    }
    __syncthreads();

    if (warp < 8 && par == 0) {
        #pragma unroll
        for (int hp = 0; hp < 8; ++hp) {
            u64 s = sig2s(add2(acc[hp], part2[hp * 128 + m * 16 + row]));
            float s0, s1; unpack2(s, s0, s1);
            h2s[row * 129 + m * 16 + hp * 2]     = s0;
            h2s[row * 129 + m * 16 + hp * 2 + 1] = s1;
        }
    }
    __syncthreads();

    // ---- root partial: warp w (<8) covers k in [w*16, (w+1)*16) ----
    if (warp < 8) {
        u64 racc[8];
        #pragma unroll
        for (int hp = 0; hp < 8; ++hp) racc[hp] = 0ull;
        #pragma unroll
        for (int jj = 0; jj < 16; ++jj) {
            int jg = warp * 16 + jj;
            float a = h2s[row * 129 + jg];
            u64 d = pack2(a, a);
            const ulonglong2* wr = (const ulonglong2*)(w3s + jg * 16);
            ulonglong2 w0 = wr[0], w1 = wr[1], w2v = wr[2], w3v = wr[3];
            racc[0] = ffma2(d, w0.x,  racc[0]);
            racc[1] = ffma2(d, w0.y,  racc[1]);
            racc[2] = ffma2(d, w1.x,  racc[2]);
            racc[3] = ffma2(d, w1.y,  racc[3]);
            racc[4] = ffma2(d, w2v.x, racc[4]);
            racc[5] = ffma2(d, w2v.y, racc[5]);
            racc[6] = ffma2(d, w3v.x, racc[6]);
            racc[7] = ffma2(d, w3v.y, racc[7]);
        }
        if (par == 0) {
            #pragma unroll
            for (int hp = 0; hp < 8; ++hp)
                part[hp * 128 + warp * 16 + row] = racc[hp];
        }
    }
    __syncthreads();

    // ---- reduce: warp w (<8) owns h-pair hp=w ----
    if (warp < 8 && par == 0) {
        u64 s = part[warp * 128 + row];
        #pragma unroll
        for (int ww = 1; ww < 8; ++ww)
            s = add2(s, part[warp * 128 + ww * 16 + row]);
        u64 sg = sig2s(s);
        float s0, s1; unpack2(sg, s0, s1);
        float c = s0 * __ldg(Wf + warp * 2) + s1 * __ldg(Wf + warp * 2 + 1);
        fpart[warp * 16 + row] = c;
    }
    __syncthreads();

    if (warp == 0 && par == 0) {
        float a = fpart[row];
        #pragma unroll
        for (int ww = 1; ww < 8; ++ww) a += fpart[ww * 16 + row];
        out[row0 + row] = a;
    }
}

static const int K2_SMEM = (16384 + 2048 + H2S_FLOATS) * 4 + 1024 * 8 + 1024 * 8 + 128 * 4;

extern "C" void kernel_launch(void* const* d_in, const int* in_sizes, int n_in,
                              void* d_out, int out_size)
{
    const float* x  = (const float*)d_in[0];
    const float* Wg = (const float*)d_in[1];
    const float* bg = (const float*)d_in[2];
    const float* W0 = (const float*)d_in[3];
    const float* W1 = (const float*)d_in[4];
    const float* W2 = (const float*)d_in[5];
    const float* W3 = (const float*)d_in[6];
    const float* Wf = (const float*)d_in[7];
    float* out = (float*)d_out;

    cudaFuncSetAttribute(k2, cudaFuncAttributeMaxDynamicSharedMemorySize, K2_SMEM);

    dim3 g1(8, 64);
    k1<<<g1, 256>>>(x, Wg, bg, W0, W1);
    k2<<<256, 512, K2_SMEM>>>(W2, W3, Wf, out);
}